// round 3
// baseline (speedup 1.0000x reference)
#include <cuda_runtime.h>
#include <math.h>

#define NB   8
#define LOW  64
#define NN   4096
#define HID  16

// ----------------- device scratch -----------------
__device__ __align__(16) float g_xl[NB*NN];
__device__ __align__(16) float g_h1[NB*64*NN];
__device__ __align__(16) float g_nodes[NB*NN*HID];
__device__ __align__(16) float g_sq[NB*NN];          // holds 0.5*|node|^2
__device__ __align__(16) float g_xp[NB*NN*HID];
__device__ __align__(16) float g_asr[NB*NN*4];
__device__ __align__(16) float g_adt[NB*NN*4];
__device__ __align__(16) float g_p[NB*NN*HID];
__device__ __align__(16) float g_outlow[NB*NN];
__device__ __align__(16) float g_w1t[9*64];
__device__ __align__(16) float g_beta1[64];
__device__ __align__(16) float g_Wt2[64*9*16];
__device__ __align__(16) float g_beta2[16];
__device__ __align__(16) float g_Wu2t[128*16];

// ----------------- packed f32x2 helpers -----------------
__device__ __forceinline__ unsigned long long ffma2(unsigned long long a,
                                                    unsigned long long b,
                                                    unsigned long long c) {
    unsigned long long d;
    asm("fma.rn.f32x2 %0, %1, %2, %3;" : "=l"(d) : "l"(a), "l"(b), "l"(c));
    return d;
}
__device__ __forceinline__ unsigned long long pk2(float lo, float hi) {
    unsigned long long u;
    asm("mov.b64 %0, {%1, %2};" : "=l"(u) : "r"(__float_as_uint(lo)), "r"(__float_as_uint(hi)));
    return u;
}
__device__ __forceinline__ float unpksum(unsigned long long u) {
    float a, b;
    asm("mov.b64 {%0, %1}, %2;" : "=f"(a), "=f"(b) : "l"(u));
    return a + b;
}
__device__ __forceinline__ void unpk(unsigned long long u, float& a, float& b) {
    asm("mov.b64 {%0, %1}, %2;" : "=f"(a), "=f"(b) : "l"(u));
}

// ----------------- prep: fold BN, transpose weights -----------------
__global__ void prepk(const float* __restrict__ W1, const float* __restrict__ b1,
                      const float* __restrict__ g1, const float* __restrict__ be1,
                      const float* __restrict__ m1, const float* __restrict__ v1,
                      const float* __restrict__ W2, const float* __restrict__ b2,
                      const float* __restrict__ g2, const float* __restrict__ be2,
                      const float* __restrict__ m2, const float* __restrict__ v2,
                      const float* __restrict__ Wu2)
{
    __shared__ float a2[16];
    int t = threadIdx.x;
    if (t < 64) {
        float a = g1[t] / sqrtf(v1[t] + 1e-5f);
        g_beta1[t] = (b1[t] - m1[t]) * a + be1[t];
        #pragma unroll
        for (int tp = 0; tp < 9; tp++) g_w1t[tp*64 + t] = W1[t*9 + tp] * a;
    }
    if (t < 16) {
        float a = g2[t] / sqrtf(v2[t] + 1e-5f);
        a2[t] = a;
        g_beta2[t] = (b2[t] - m2[t]) * a + be2[t];
    }
    __syncthreads();
    for (int i = t; i < 64*9*16; i += 256) {
        int oc = i & 15; int rest = i >> 4; int tp = rest % 9; int ci = rest / 9;
        g_Wt2[i] = W2[(oc*64 + ci)*9 + tp] * a2[oc];
    }
    for (int i = t; i < 2048; i += 256) {
        int h = i >> 4, o = i & 15;
        g_Wu2t[i] = Wu2[o*128 + h];
    }
}

// ----------------- antialiased bilinear 256 -> 64 -----------------
__global__ void downk(const float* __restrict__ x)
{
    int idx = blockIdx.x * 256 + threadIdx.x;
    int b = idx >> 12, oy = (idx >> 6) & 63, ox = idx & 63;
    float wy[8], wx[8]; float sy = 0.f, sx = 0.f;
    #pragma unroll
    for (int d = 0; d < 8; d++) {
        float w = 1.f - 0.25f * fabsf((float)d - 3.5f);
        int jy = 4*oy + d - 2;
        int jx = 4*ox + d - 2;
        wy[d] = (jy >= 0 && jy < 256) ? w : 0.f; sy += wy[d];
        wx[d] = (jx >= 0 && jx < 256) ? w : 0.f; sx += wx[d];
    }
    const float* src = x + (size_t)b * 65536;
    float acc = 0.f;
    #pragma unroll
    for (int dy = 0; dy < 8; dy++) {
        int jy = 4*oy + dy - 2; jy = jy < 0 ? 0 : (jy > 255 ? 255 : jy);
        float rowacc = 0.f;
        #pragma unroll
        for (int dx = 0; dx < 8; dx++) {
            int jx = 4*ox + dx - 2; jx = jx < 0 ? 0 : (jx > 255 ? 255 : jx);
            rowacc = fmaf(wx[dx], src[jy*256 + jx], rowacc);
        }
        acc = fmaf(wy[dy], rowacc, acc);
    }
    g_xl[idx] = acc / (sy * sx);
}

// ----------------- conv1: 1->64, 3x3 SAME (packed f32x2) -----------------
__global__ void conv1k()
{
    __shared__ __align__(16) float sw[576];
    __shared__ __align__(16) float sb[64];
    int t = threadIdx.x;
    for (int i = t; i < 576; i += 256) sw[i] = g_w1t[i];
    if (t < 64) sb[t] = g_beta1[t];
    __syncthreads();
    int idx = blockIdx.x * 256 + t;
    int b = idx >> 12, y = (idx >> 6) & 63, xx = idx & 63;
    float vin[9];
    #pragma unroll
    for (int dy = 0; dy < 3; dy++)
        #pragma unroll
        for (int dx = 0; dx < 3; dx++) {
            int yy = y + dy - 1, xc = xx + dx - 1;
            vin[dy*3+dx] = (yy >= 0 && yy < 64 && xc >= 0 && xc < 64)
                           ? g_xl[b*4096 + yy*64 + xc] : 0.f;
        }
    unsigned long long acc[32];
    {
        const ulonglong2* bp = (const ulonglong2*)sb;
        #pragma unroll
        for (int q = 0; q < 16; q++) { ulonglong2 v = bp[q]; acc[2*q] = v.x; acc[2*q+1] = v.y; }
    }
    #pragma unroll
    for (int tp = 0; tp < 9; tp++) {
        float v = vin[tp];
        unsigned long long vp = pk2(v, v);
        const ulonglong2* wp = (const ulonglong2*)&sw[tp*64];
        #pragma unroll
        for (int q = 0; q < 16; q++) {
            ulonglong2 w = wp[q];
            acc[2*q]   = ffma2(vp, w.x, acc[2*q]);
            acc[2*q+1] = ffma2(vp, w.y, acc[2*q+1]);
        }
    }
    size_t base = ((size_t)b*64)*4096 + y*64 + xx;
    #pragma unroll
    for (int k = 0; k < 32; k++) {
        float lo, hi; unpk(acc[k], lo, hi);
        g_h1[base + (size_t)(2*k)*4096]   = fmaxf(lo, 0.f);
        g_h1[base + (size_t)(2*k+1)*4096] = fmaxf(hi, 0.f);
    }
}

// ----------------- conv2: 64->16, 3x3 SAME (packed), 256 blocks x 128 thr -----------------
__global__ void __launch_bounds__(128) conv2k()
{
    __shared__ __align__(16) float swt[64*9*16];   // 36 KB
    __shared__ __align__(16) float tile[8*10*18];  // 5.6 KB
    __shared__ float sbeta[16];
    int t = threadIdx.x;
    {
        float4* s4 = (float4*)swt;
        const float4* g4 = (const float4*)g_Wt2;
        for (int i = t; i < 2304; i += 128) s4[i] = g4[i];
    }
    if (t < 16) sbeta[t] = g_beta2[t];
    int b = blockIdx.z; int y0 = blockIdx.y * 8; int x0 = blockIdx.x * 16;
    int ty = t >> 4, tx = t & 15;
    unsigned long long acc[8];
    #pragma unroll
    for (int k = 0; k < 8; k++) acc[k] = 0ull;
    for (int cc = 0; cc < 8; cc++) {
        __syncthreads();
        for (int i = t; i < 1440; i += 128) {
            int cl = i / 180; int rem = i - cl*180; int rr = rem / 18; int c = rem - rr*18;
            int yy = y0 + rr - 1, xc = x0 + c - 1;
            float v = 0.f;
            if (yy >= 0 && yy < 64 && xc >= 0 && xc < 64)
                v = g_h1[(((size_t)b*64 + (cc*8 + cl))*64 + yy)*64 + xc];
            tile[i] = v;
        }
        __syncthreads();
        #pragma unroll
        for (int cl = 0; cl < 8; cl++) {
            int ci = cc*8 + cl;
            float v[9];
            #pragma unroll
            for (int dy = 0; dy < 3; dy++)
                #pragma unroll
                for (int dx = 0; dx < 3; dx++)
                    v[dy*3+dx] = tile[cl*180 + (ty+dy)*18 + (tx+dx)];
            #pragma unroll
            for (int tp = 0; tp < 9; tp++) {
                unsigned long long vp = pk2(v[tp], v[tp]);
                const ulonglong2* w2 = (const ulonglong2*)&swt[ci*144 + tp*16];
                ulonglong2 wa = w2[0], wb = w2[1], wc = w2[2], wd = w2[3];
                acc[0] = ffma2(vp, wa.x, acc[0]); acc[1] = ffma2(vp, wa.y, acc[1]);
                acc[2] = ffma2(vp, wb.x, acc[2]); acc[3] = ffma2(vp, wb.y, acc[3]);
                acc[4] = ffma2(vp, wc.x, acc[4]); acc[5] = ffma2(vp, wc.y, acc[5]);
                acc[6] = ffma2(vp, wd.x, acc[6]); acc[7] = ffma2(vp, wd.y, acc[7]);
            }
        }
    }
    float out[16];
    #pragma unroll
    for (int k = 0; k < 8; k++) unpk(acc[k], out[2*k], out[2*k+1]);
    float s = 0.f;
    #pragma unroll
    for (int c = 0; c < 16; c++) {
        float vv = fmaxf(out[c] + sbeta[c], 0.f);
        out[c] = vv; s = fmaf(vv, vv, s);
    }
    int n = (y0 + ty)*64 + (x0 + tx);
    float4* dst = (float4*)&g_nodes[((size_t)b*NN + n)*16];
    dst[0] = make_float4(out[0],out[1],out[2],out[3]);
    dst[1] = make_float4(out[4],out[5],out[6],out[7]);
    dst[2] = make_float4(out[8],out[9],out[10],out[11]);
    dst[3] = make_float4(out[12],out[13],out[14],out[15]);
    g_sq[(size_t)b*NN + n] = 0.5f * s;
}

// ----------------- GAT feature transform -----------------
__global__ void featk(const float* __restrict__ Wg, const float* __restrict__ a_src,
                      const float* __restrict__ a_dst)
{
    __shared__ float sWg[256];
    __shared__ float ssrc[16], sdst[16];
    int t = threadIdx.x;
    sWg[t] = Wg[t];
    if (t < 16) { ssrc[t] = a_src[t]; sdst[t] = a_dst[t]; }
    __syncthreads();
    int idx = blockIdx.x * 256 + t;
    const float4* np = (const float4*)&g_nodes[(size_t)idx*16];
    float n[16];
    float4 v0 = np[0], v1 = np[1], v2 = np[2], v3 = np[3];
    n[0]=v0.x; n[1]=v0.y; n[2]=v0.z; n[3]=v0.w;
    n[4]=v1.x; n[5]=v1.y; n[6]=v1.z; n[7]=v1.w;
    n[8]=v2.x; n[9]=v2.y; n[10]=v2.z; n[11]=v2.w;
    n[12]=v3.x; n[13]=v3.y; n[14]=v3.z; n[15]=v3.w;
    float xo[16];
    #pragma unroll
    for (int o = 0; o < 16; o++) {
        float a = 0.f;
        #pragma unroll
        for (int c = 0; c < 16; c++) a = fmaf(n[c], sWg[o*16 + c], a);
        xo[o] = a;
    }
    float4* xpd = (float4*)&g_xp[(size_t)idx*16];
    xpd[0] = make_float4(xo[0],xo[1],xo[2],xo[3]);
    xpd[1] = make_float4(xo[4],xo[5],xo[6],xo[7]);
    xpd[2] = make_float4(xo[8],xo[9],xo[10],xo[11]);
    xpd[3] = make_float4(xo[12],xo[13],xo[14],xo[15]);
    float4 av, dv;
    av.x = xo[0]*ssrc[0] + xo[1]*ssrc[1] + xo[2]*ssrc[2] + xo[3]*ssrc[3];
    av.y = xo[4]*ssrc[4] + xo[5]*ssrc[5] + xo[6]*ssrc[6] + xo[7]*ssrc[7];
    av.z = xo[8]*ssrc[8] + xo[9]*ssrc[9] + xo[10]*ssrc[10] + xo[11]*ssrc[11];
    av.w = xo[12]*ssrc[12] + xo[13]*ssrc[13] + xo[14]*ssrc[14] + xo[15]*ssrc[15];
    dv.x = xo[0]*sdst[0] + xo[1]*sdst[1] + xo[2]*sdst[2] + xo[3]*sdst[3];
    dv.y = xo[4]*sdst[4] + xo[5]*sdst[5] + xo[6]*sdst[6] + xo[7]*sdst[7];
    dv.z = xo[8]*sdst[8] + xo[9]*sdst[9] + xo[10]*sdst[10] + xo[11]*sdst[11];
    dv.w = xo[12]*sdst[12] + xo[13]*sdst[13] + xo[14]*sdst[14] + xo[15]*sdst[15];
    ((float4*)g_asr)[idx] = av;
    ((float4*)g_adt)[idx] = dv;
}

// ----------------- kNN (top-8) + GAT: 2 rows/thread, 4-way candidate split -----------------
__global__ void __launch_bounds__(256) knnk(const float* __restrict__ bg)
{
    // phase 1: tiles (4 splits x 128 cand x 64B = 32KB) + half-sq (2KB)
    // phase 2 (alias): dist lists 16KB + idx lists 16KB
    __shared__ __align__(16) char sbuf[32768 + 2048];
    float4* scand = (float4*)sbuf;                 // [ (s*128+j)*4 + q ]
    float*  ssqh  = (float*)(sbuf + 32768);        // [ s*128 + j ]

    int t = threadIdx.x;
    int b = blockIdx.y;
    int base = blockIdx.x * 128;                   // row base (in-batch)
    int s = t >> 6;                                // candidate split 0..3
    int rp = t & 63;
    int lr0 = rp*2, lr1 = rp*2 + 1;
    int rowA = base + lr0, rowB = base + lr1;

    const ulonglong2* apA = (const ulonglong2*)(g_nodes + ((size_t)b*NN + rowA)*16);
    const ulonglong2* apB = (const ulonglong2*)(g_nodes + ((size_t)b*NN + rowB)*16);
    ulonglong2 a0 = apA[0], a1 = apA[1], a2 = apA[2], a3 = apA[3];
    ulonglong2 b0 = apB[0], b1 = apB[1], b2 = apB[2], b3 = apB[3];
    unsigned long long rA[8] = {a0.x,a0.y,a1.x,a1.y,a2.x,a2.y,a3.x,a3.y};
    unsigned long long rB[8] = {b0.x,b0.y,b1.x,b1.y,b2.x,b2.y,b3.x,b3.y};

    float bdA[8], bdB[8]; int biA[8], biB[8];
    #pragma unroll
    for (int p = 0; p < 8; p++) { bdA[p] = 3e38f; bdB[p] = 3e38f; biA[p] = 0; biB[p] = 0; }

    for (int tt = 0; tt < 8; tt++) {
        __syncthreads();
        #pragma unroll
        for (int cc2 = 0; cc2 < 2; cc2++) {
            int c = t*2 + cc2; int sc = c >> 7, j = c & 127;
            int g = sc*1024 + tt*128 + j;
            const float4* src = (const float4*)g_nodes + ((size_t)b*NN + g)*4;
            scand[c*4+0] = src[0]; scand[c*4+1] = src[1];
            scand[c*4+2] = src[2]; scand[c*4+3] = src[3];
            ssqh[c] = g_sq[b*NN + g];
        }
        __syncthreads();
        int cbase = s*1024 + tt*128;
        #pragma unroll 2
        for (int j = 0; j < 128; j++) {
            const ulonglong2* cp = (const ulonglong2*)(scand + (s*128 + j)*4);
            ulonglong2 q0 = cp[0], q1 = cp[1], q2 = cp[2], q3 = cp[3];
            unsigned long long aA = ffma2(rA[0], q0.x, 0ull);
            unsigned long long aB = ffma2(rB[0], q0.x, 0ull);
            aA = ffma2(rA[1], q0.y, aA); aB = ffma2(rB[1], q0.y, aB);
            aA = ffma2(rA[2], q1.x, aA); aB = ffma2(rB[2], q1.x, aB);
            aA = ffma2(rA[3], q1.y, aA); aB = ffma2(rB[3], q1.y, aB);
            aA = ffma2(rA[4], q2.x, aA); aB = ffma2(rB[4], q2.x, aB);
            aA = ffma2(rA[5], q2.y, aA); aB = ffma2(rB[5], q2.y, aB);
            aA = ffma2(rA[6], q3.x, aA); aB = ffma2(rB[6], q3.x, aB);
            aA = ffma2(rA[7], q3.y, aA); aB = ffma2(rB[7], q3.y, aB);
            float sq = ssqh[s*128 + j];
            float dA = sq - unpksum(aA);
            float dB = sq - unpksum(aB);
            int jj = cbase + j;
            if (dA < bdA[7] && jj != rowA) {
                bdA[7] = dA; biA[7] = jj;
                #pragma unroll
                for (int p = 7; p > 0; p--)
                    if (bdA[p] < bdA[p-1]) {
                        float td = bdA[p]; bdA[p] = bdA[p-1]; bdA[p-1] = td;
                        int ti = biA[p]; biA[p] = biA[p-1]; biA[p-1] = ti;
                    }
            }
            if (dB < bdB[7] && jj != rowB) {
                bdB[7] = dB; biB[7] = jj;
                #pragma unroll
                for (int p = 7; p > 0; p--)
                    if (bdB[p] < bdB[p-1]) {
                        float td = bdB[p]; bdB[p] = bdB[p-1]; bdB[p-1] = td;
                        int ti = biB[p]; biB[p] = biB[p-1]; biB[p-1] = ti;
                    }
            }
        }
    }

    // ---- write per-split lists: layout [s][p][lr] ----
    __syncthreads();
    float* ld  = (float*)sbuf;               // 4096 floats
    int*   li_ = (int*)(sbuf + 16384);       // 4096 ints
    #pragma unroll
    for (int p = 0; p < 8; p++) {
        ld [((s*8+p)<<7) + lr0] = bdA[p];  li_[((s*8+p)<<7) + lr0] = biA[p];
        ld [((s*8+p)<<7) + lr1] = bdB[p];  li_[((s*8+p)<<7) + lr1] = biB[p];
    }
    __syncthreads();

    if (t >= 128) return;
    // ---- 4-way merge (tie -> lowest split = lowest index) ----
    int row = base + t;
    int ptr0 = 0, ptr1 = 0, ptr2 = 0, ptr3 = 0;
    int nb[8];
    #pragma unroll
    for (int k = 0; k < 8; k++) {
        float d0 = ld[((     ptr0)<<7) + t];
        float d1 = ld[(( 8 + ptr1)<<7) + t];
        float d2 = ld[((16 + ptr2)<<7) + t];
        float d3 = ld[((24 + ptr3)<<7) + t];
        float best = d0; int bs = 0;
        if (d1 < best) { best = d1; bs = 1; }
        if (d2 < best) { best = d2; bs = 2; }
        if (d3 < best) { best = d3; bs = 3; }
        int pp = bs == 0 ? ptr0 : bs == 1 ? ptr1 : bs == 2 ? ptr2 : ptr3;
        nb[k] = li_[((bs*8 + pp)<<7) + t];
        if (bs == 0) ptr0++; else if (bs == 1) ptr1++; else if (bs == 2) ptr2++; else ptr3++;
    }

    // ---- GAT aggregation over 8 neighbors + self ----
    float4 adv = ((const float4*)g_adt)[b*NN + row];
    float ad0 = adv.x, ad1 = adv.y, ad2 = adv.z, ad3 = adv.w;
    int idxs[9];
    #pragma unroll
    for (int k = 0; k < 8; k++) idxs[k] = nb[k];
    idxs[8] = row;
    float lg[36];
    float m0 = -3e38f, m1 = -3e38f, m2 = -3e38f, m3 = -3e38f;
    #pragma unroll
    for (int k = 0; k < 9; k++) {
        float4 av = ((const float4*)g_asr)[b*NN + idxs[k]];
        float l0 = av.x + ad0; l0 = l0 > 0.f ? l0 : 0.2f*l0;
        float l1 = av.y + ad1; l1 = l1 > 0.f ? l1 : 0.2f*l1;
        float l2 = av.z + ad2; l2 = l2 > 0.f ? l2 : 0.2f*l2;
        float l3 = av.w + ad3; l3 = l3 > 0.f ? l3 : 0.2f*l3;
        lg[k*4+0] = l0; lg[k*4+1] = l1; lg[k*4+2] = l2; lg[k*4+3] = l3;
        m0 = fmaxf(m0, l0); m1 = fmaxf(m1, l1); m2 = fmaxf(m2, l2); m3 = fmaxf(m3, l3);
    }
    float s0 = 0.f, s1 = 0.f, s2 = 0.f, s3 = 0.f;
    float out[16];
    #pragma unroll
    for (int c = 0; c < 16; c++) out[c] = 0.f;
    #pragma unroll
    for (int k = 0; k < 9; k++) {
        float w0 = expf(lg[k*4+0] - m0);
        float w1 = expf(lg[k*4+1] - m1);
        float w2 = expf(lg[k*4+2] - m2);
        float w3 = expf(lg[k*4+3] - m3);
        s0 += w0; s1 += w1; s2 += w2; s3 += w3;
        const float4* xp4 = (const float4*)g_xp + ((size_t)b*NN + idxs[k])*4;
        float4 x0 = xp4[0], x1 = xp4[1], x2 = xp4[2], x3 = xp4[3];
        out[0]  = fmaf(w0, x0.x, out[0]);  out[1]  = fmaf(w0, x0.y, out[1]);
        out[2]  = fmaf(w0, x0.z, out[2]);  out[3]  = fmaf(w0, x0.w, out[3]);
        out[4]  = fmaf(w1, x1.x, out[4]);  out[5]  = fmaf(w1, x1.y, out[5]);
        out[6]  = fmaf(w1, x1.z, out[6]);  out[7]  = fmaf(w1, x1.w, out[7]);
        out[8]  = fmaf(w2, x2.x, out[8]);  out[9]  = fmaf(w2, x2.y, out[9]);
        out[10] = fmaf(w2, x2.z, out[10]); out[11] = fmaf(w2, x2.w, out[11]);
        out[12] = fmaf(w3, x3.x, out[12]); out[13] = fmaf(w3, x3.y, out[13]);
        out[14] = fmaf(w3, x3.z, out[14]); out[15] = fmaf(w3, x3.w, out[15]);
    }
    float inv0 = 1.f/s0, inv1 = 1.f/s1, inv2 = 1.f/s2, inv3 = 1.f/s3;
    float res[16];
    #pragma unroll
    for (int c = 0; c < 4;  c++) res[c] = fmaxf(out[c]*inv0 + bg[c], 0.f);
    #pragma unroll
    for (int c = 4; c < 8;  c++) res[c] = fmaxf(out[c]*inv1 + bg[c], 0.f);
    #pragma unroll
    for (int c = 8; c < 12; c++) res[c] = fmaxf(out[c]*inv2 + bg[c], 0.f);
    #pragma unroll
    for (int c = 12; c < 16; c++) res[c] = fmaxf(out[c]*inv3 + bg[c], 0.f);
    float4* pd = (float4*)g_p + ((size_t)b*NN + row)*4;
    pd[0] = make_float4(res[0],res[1],res[2],res[3]);
    pd[1] = make_float4(res[4],res[5],res[6],res[7]);
    pd[2] = make_float4(res[8],res[9],res[10],res[11]);
    pd[3] = make_float4(res[12],res[13],res[14],res[15]);
}

// ----------------- update MLP + fire mask + output conv + sigmoid (packed) -----------------
__global__ void updk(const float* __restrict__ fire, const float* __restrict__ Wu1,
                     const float* __restrict__ bu1, const float* __restrict__ bu2,
                     const float* __restrict__ Wo,  const float* __restrict__ bo)
{
    __shared__ __align__(16) float sW1[2048];
    __shared__ __align__(16) float sW2[2048];
    __shared__ __align__(16) float sb2[16];
    __shared__ __align__(16) float sWo[16];
    __shared__ float sb1[128];
    __shared__ float sbo;
    int t = threadIdx.x;
    for (int i = t; i < 2048; i += 256) { sW1[i] = Wu1[i]; sW2[i] = g_Wu2t[i]; }
    if (t < 128) sb1[t] = bu1[t];
    if (t < 16)  { sb2[t] = bu2[t]; sWo[t] = Wo[t]; }
    if (t == 0)  sbo = bo[0];
    __syncthreads();
    int idx = blockIdx.x * 256 + t;
    const ulonglong2* pp = (const ulonglong2*)(g_p + (size_t)idx*16);
    ulonglong2 p0 = pp[0], p1 = pp[1], p2 = pp[2], p3 = pp[3];
    unsigned long long pk[8] = {p0.x,p0.y,p1.x,p1.y,p2.x,p2.y,p3.x,p3.y};
    unsigned long long u[8];
    {
        const ulonglong2* b2p = (const ulonglong2*)sb2;
        ulonglong2 u0 = b2p[0], u1 = b2p[1];
        u[0]=u0.x; u[1]=u0.y; u[2]=u1.x; u[3]=u1.y;
        ulonglong2 u2 = b2p[2], u3 = b2p[3];
        u[4]=u2.x; u[5]=u2.y; u[6]=u3.x; u[7]=u3.y;
    }
    #pragma unroll 2
    for (int h = 0; h < 128; h++) {
        const ulonglong2* w1p = (const ulonglong2*)&sW1[h*16];
        ulonglong2 wa = w1p[0], wb = w1p[1], wc = w1p[2], wd = w1p[3];
        unsigned long long acc = ffma2(pk[0], wa.x, 0ull);
        acc = ffma2(pk[1], wa.y, acc);
        acc = ffma2(pk[2], wb.x, acc);
        acc = ffma2(pk[3], wb.y, acc);
        acc = ffma2(pk[4], wc.x, acc);
        acc = ffma2(pk[5], wc.y, acc);
        acc = ffma2(pk[6], wd.x, acc);
        acc = ffma2(pk[7], wd.y, acc);
        float a = unpksum(acc) + sb1[h];
        a = fmaxf(a, 0.f);
        unsigned long long ap = pk2(a, a);
        const ulonglong2* w2p = (const ulonglong2*)&sW2[h*16];
        ulonglong2 va = w2p[0], vb = w2p[1], vc = w2p[2], vd = w2p[3];
        u[0] = ffma2(ap, va.x, u[0]); u[1] = ffma2(ap, va.y, u[1]);
        u[2] = ffma2(ap, vb.x, u[2]); u[3] = ffma2(ap, vb.y, u[3]);
        u[4] = ffma2(ap, vc.x, u[4]); u[5] = ffma2(ap, vc.y, u[5]);
        u[6] = ffma2(ap, vd.x, u[6]); u[7] = ffma2(ap, vd.y, u[7]);
    }
    float mask = fire[idx] < 0.5f ? 1.f : 0.f;
    unsigned long long mp = pk2(mask, mask);
    const ulonglong2* hp = (const ulonglong2*)(g_nodes + (size_t)idx*16);
    ulonglong2 h0 = hp[0], h1 = hp[1], h2 = hp[2], h3 = hp[3];
    unsigned long long hk[8] = {h0.x,h0.y,h1.x,h1.y,h2.x,h2.y,h3.x,h3.y};
    const ulonglong2* wop = (const ulonglong2*)sWo;
    ulonglong2 wo0 = wop[0], wo1 = wop[1], wo2 = wop[2], wo3 = wop[3];
    unsigned long long wk[8] = {wo0.x,wo0.y,wo1.x,wo1.y,wo2.x,wo2.y,wo3.x,wo3.y};
    unsigned long long accS = 0ull;
    #pragma unroll
    for (int k = 0; k < 8; k++) {
        unsigned long long hn = ffma2(mp, u[k], hk[k]);
        accS = ffma2(wk[k], hn, accS);
    }
    float ss = unpksum(accS) + sbo;
    g_outlow[idx] = 1.f / (1.f + expf(-ss));
}

// ----------------- bilinear 64 -> 256 -----------------
__global__ void upk(float* __restrict__ out)
{
    int idx = blockIdx.x * 256 + threadIdx.x;
    int b = idx >> 16, oy = (idx >> 8) & 255, ox = idx & 255;
    float sy = (oy + 0.5f) * 0.25f - 0.5f;
    float sx = (ox + 0.5f) * 0.25f - 0.5f;
    int y0 = (int)floorf(sy); float fy = sy - (float)y0;
    int x0 = (int)floorf(sx); float fx = sx - (float)x0;
    float wy0 = 1.f - fy, wy1 = fy; int y1 = y0 + 1;
    float wx0 = 1.f - fx, wx1 = fx; int x1 = x0 + 1;
    if (y0 < 0)  { wy0 = 0.f; y0 = 0; }
    if (y1 > 63) { wy1 = 0.f; y1 = 63; }
    if (x0 < 0)  { wx0 = 0.f; x0 = 0; }
    if (x1 > 63) { wx1 = 0.f; x1 = 63; }
    const float* src = g_outlow + b * 4096;
    float v = wy0 * (wx0 * src[y0*64 + x0] + wx1 * src[y0*64 + x1])
            + wy1 * (wx0 * src[y1*64 + x0] + wx1 * src[y1*64 + x1]);
    out[idx] = v / ((wy0 + wy1) * (wx0 + wx1));
}

// ----------------- launch -----------------
extern "C" void kernel_launch(void* const* d_in, const int* in_sizes, int n_in,
                              void* d_out, int out_size)
{
    (void)in_sizes; (void)n_in; (void)out_size;
    const float* x    = (const float*)d_in[0];
    const float* fire = (const float*)d_in[1];
    const float* W1   = (const float*)d_in[2];
    const float* b1   = (const float*)d_in[3];
    const float* g1   = (const float*)d_in[4];
    const float* be1  = (const float*)d_in[5];
    const float* m1   = (const float*)d_in[6];
    const float* v1   = (const float*)d_in[7];
    const float* W2   = (const float*)d_in[8];
    const float* b2   = (const float*)d_in[9];
    const float* g2   = (const float*)d_in[10];
    const float* be2  = (const float*)d_in[11];
    const float* m2   = (const float*)d_in[12];
    const float* v2   = (const float*)d_in[13];
    const float* Wg   = (const float*)d_in[14];
    const float* a_src= (const float*)d_in[15];
    const float* a_dst= (const float*)d_in[16];
    const float* bg   = (const float*)d_in[17];
    const float* Wu1  = (const float*)d_in[18];
    const float* bu1  = (const float*)d_in[19];
    const float* Wu2  = (const float*)d_in[20];
    const float* bu2  = (const float*)d_in[21];
    const float* Wo   = (const float*)d_in[22];
    const float* bo   = (const float*)d_in[23];
    float* out = (float*)d_out;

    prepk<<<1, 256>>>(W1, b1, g1, be1, m1, v1, W2, b2, g2, be2, m2, v2, Wu2);
    downk<<<128, 256>>>(x);
    conv1k<<<128, 256>>>();
    conv2k<<<dim3(4, 8, 8), 128>>>();
    featk<<<128, 256>>>(Wg, a_src, a_dst);
    knnk<<<dim3(32, 8), 256>>>(bg);
    updk<<<128, 256>>>(fire, Wu1, bu1, bu2, Wo, bo);
    upk<<<2048, 256>>>(out);
}

// round 4
// speedup vs baseline: 1.0521x; 1.0521x over previous
#include <cuda_runtime.h>
#include <math.h>

#define NB   8
#define LOW  64
#define NN   4096
#define HID  16

// ----------------- device scratch -----------------
__device__ __align__(16) float g_xl[NB*NN];
__device__ __align__(16) float g_h1[NB*64*NN];
__device__ __align__(16) float g_nodes[NB*NN*HID];
__device__ __align__(16) float g_sq[NB*NN];          // 0.5*|node|^2
__device__ __align__(16) float g_xp[NB*NN*HID];
__device__ __align__(16) float g_asr[NB*NN*4];
__device__ __align__(16) float g_adt[NB*NN*4];
__device__ __align__(16) float g_p[NB*NN*HID];
__device__ __align__(16) float g_outlow[NB*NN];
__device__ __align__(16) float g_w1t[9*64];
__device__ __align__(16) float g_beta1[64];
__device__ __align__(16) float g_Wt2[64*9*16];
__device__ __align__(16) float g_beta2[16];
__device__ __align__(16) float g_Wu2t[128*16];

// ----------------- packed f32x2 helpers -----------------
__device__ __forceinline__ unsigned long long ffma2(unsigned long long a,
                                                    unsigned long long b,
                                                    unsigned long long c) {
    unsigned long long d;
    asm("fma.rn.f32x2 %0, %1, %2, %3;" : "=l"(d) : "l"(a), "l"(b), "l"(c));
    return d;
}
__device__ __forceinline__ unsigned long long pk2(float lo, float hi) {
    unsigned long long u;
    asm("mov.b64 %0, {%1, %2};" : "=l"(u) : "r"(__float_as_uint(lo)), "r"(__float_as_uint(hi)));
    return u;
}
__device__ __forceinline__ float unpksum(unsigned long long u) {
    float a, b;
    asm("mov.b64 {%0, %1}, %2;" : "=f"(a), "=f"(b) : "l"(u));
    return a + b;
}
__device__ __forceinline__ void unpk(unsigned long long u, float& a, float& b) {
    asm("mov.b64 {%0, %1}, %2;" : "=f"(a), "=f"(b) : "l"(u));
}

// ----------------- prep -----------------
__global__ void prepk(const float* __restrict__ W1, const float* __restrict__ b1,
                      const float* __restrict__ g1, const float* __restrict__ be1,
                      const float* __restrict__ m1, const float* __restrict__ v1,
                      const float* __restrict__ W2, const float* __restrict__ b2,
                      const float* __restrict__ g2, const float* __restrict__ be2,
                      const float* __restrict__ m2, const float* __restrict__ v2,
                      const float* __restrict__ Wu2)
{
    __shared__ float a2[16];
    int t = threadIdx.x;
    if (t < 64) {
        float a = g1[t] / sqrtf(v1[t] + 1e-5f);
        g_beta1[t] = (b1[t] - m1[t]) * a + be1[t];
        #pragma unroll
        for (int tp = 0; tp < 9; tp++) g_w1t[tp*64 + t] = W1[t*9 + tp] * a;
    }
    if (t < 16) {
        float a = g2[t] / sqrtf(v2[t] + 1e-5f);
        a2[t] = a;
        g_beta2[t] = (b2[t] - m2[t]) * a + be2[t];
    }
    __syncthreads();
    for (int i = t; i < 64*9*16; i += 256) {
        int oc = i & 15; int rest = i >> 4; int tp = rest % 9; int ci = rest / 9;
        g_Wt2[i] = W2[(oc*64 + ci)*9 + tp] * a2[oc];
    }
    for (int i = t; i < 2048; i += 256) {
        int h = i >> 4, o = i & 15;
        g_Wu2t[i] = Wu2[o*128 + h];
    }
}

// ----------------- antialiased bilinear 256 -> 64 -----------------
__global__ void downk(const float* __restrict__ x)
{
    int idx = blockIdx.x * 256 + threadIdx.x;
    int b = idx >> 12, oy = (idx >> 6) & 63, ox = idx & 63;
    float wy[8], wx[8]; float sy = 0.f, sx = 0.f;
    #pragma unroll
    for (int d = 0; d < 8; d++) {
        float w = 1.f - 0.25f * fabsf((float)d - 3.5f);
        int jy = 4*oy + d - 2;
        int jx = 4*ox + d - 2;
        wy[d] = (jy >= 0 && jy < 256) ? w : 0.f; sy += wy[d];
        wx[d] = (jx >= 0 && jx < 256) ? w : 0.f; sx += wx[d];
    }
    const float* src = x + (size_t)b * 65536;
    float acc = 0.f;
    #pragma unroll
    for (int dy = 0; dy < 8; dy++) {
        int jy = 4*oy + dy - 2; jy = jy < 0 ? 0 : (jy > 255 ? 255 : jy);
        float rowacc = 0.f;
        #pragma unroll
        for (int dx = 0; dx < 8; dx++) {
            int jx = 4*ox + dx - 2; jx = jx < 0 ? 0 : (jx > 255 ? 255 : jx);
            rowacc = fmaf(wx[dx], src[jy*256 + jx], rowacc);
        }
        acc = fmaf(wy[dy], rowacc, acc);
    }
    g_xl[idx] = acc / (sy * sx);
}

// ----------------- conv1: 1->64, 3x3 SAME (packed f32x2) -----------------
__global__ void conv1k()
{
    __shared__ __align__(16) float sw[576];
    __shared__ __align__(16) float sb[64];
    int t = threadIdx.x;
    for (int i = t; i < 576; i += 256) sw[i] = g_w1t[i];
    if (t < 64) sb[t] = g_beta1[t];
    __syncthreads();
    int idx = blockIdx.x * 256 + t;
    int b = idx >> 12, y = (idx >> 6) & 63, xx = idx & 63;
    float vin[9];
    #pragma unroll
    for (int dy = 0; dy < 3; dy++)
        #pragma unroll
        for (int dx = 0; dx < 3; dx++) {
            int yy = y + dy - 1, xc = xx + dx - 1;
            vin[dy*3+dx] = (yy >= 0 && yy < 64 && xc >= 0 && xc < 64)
                           ? g_xl[b*4096 + yy*64 + xc] : 0.f;
        }
    unsigned long long acc[32];
    {
        const ulonglong2* bp = (const ulonglong2*)sb;
        #pragma unroll
        for (int q = 0; q < 16; q++) { ulonglong2 v = bp[q]; acc[2*q] = v.x; acc[2*q+1] = v.y; }
    }
    #pragma unroll
    for (int tp = 0; tp < 9; tp++) {
        float v = vin[tp];
        unsigned long long vp = pk2(v, v);
        const ulonglong2* wp = (const ulonglong2*)&sw[tp*64];
        #pragma unroll
        for (int q = 0; q < 16; q++) {
            ulonglong2 w = wp[q];
            acc[2*q]   = ffma2(vp, w.x, acc[2*q]);
            acc[2*q+1] = ffma2(vp, w.y, acc[2*q+1]);
        }
    }
    size_t base = ((size_t)b*64)*4096 + y*64 + xx;
    #pragma unroll
    for (int k = 0; k < 32; k++) {
        float lo, hi; unpk(acc[k], lo, hi);
        g_h1[base + (size_t)(2*k)*4096]   = fmaxf(lo, 0.f);
        g_h1[base + (size_t)(2*k+1)*4096] = fmaxf(hi, 0.f);
    }
}

// ----------------- conv2: 64->16, 3x3 SAME; 8 output channels per block -----------------
__global__ void __launch_bounds__(128) conv2k()
{
    __shared__ __align__(16) float swt[64*9*8];    // 18 KB (this half's weights)
    __shared__ __align__(16) float tile[8*10*18];  // 5.6 KB
    __shared__ float sbeta[8];
    int t = threadIdx.x;
    int xt = blockIdx.x & 3;          // 4 x-tiles of 16
    int oh = blockIdx.x >> 2;         // output-channel half (0/1)
    int b = blockIdx.z; int y0 = blockIdx.y * 8; int x0 = xt * 16;
    // load this half's weights: [ci][tap][8]
    for (int i = t; i < 4608; i += 128) {
        int o = i & 7; int rest = i >> 3; int tp = rest % 9; int ci = rest / 9;
        swt[i] = g_Wt2[ci*144 + tp*16 + oh*8 + o];
    }
    if (t < 8) sbeta[t] = g_beta2[oh*8 + t];
    int ty = t >> 4, tx = t & 15;
    unsigned long long acc[4];
    #pragma unroll
    for (int k = 0; k < 4; k++) acc[k] = 0ull;
    for (int cc = 0; cc < 8; cc++) {
        __syncthreads();
        for (int i = t; i < 1440; i += 128) {
            int cl = i / 180; int rem = i - cl*180; int rr = rem / 18; int c = rem - rr*18;
            int yy = y0 + rr - 1, xc = x0 + c - 1;
            float v = 0.f;
            if (yy >= 0 && yy < 64 && xc >= 0 && xc < 64)
                v = g_h1[(((size_t)b*64 + (cc*8 + cl))*64 + yy)*64 + xc];
            tile[i] = v;
        }
        __syncthreads();
        #pragma unroll
        for (int cl = 0; cl < 8; cl++) {
            int ci = cc*8 + cl;
            float v[9];
            #pragma unroll
            for (int dy = 0; dy < 3; dy++)
                #pragma unroll
                for (int dx = 0; dx < 3; dx++)
                    v[dy*3+dx] = tile[cl*180 + (ty+dy)*18 + (tx+dx)];
            #pragma unroll
            for (int tp = 0; tp < 9; tp++) {
                unsigned long long vp = pk2(v[tp], v[tp]);
                const ulonglong2* w2 = (const ulonglong2*)&swt[ci*72 + tp*8];
                ulonglong2 wa = w2[0], wb = w2[1];
                acc[0] = ffma2(vp, wa.x, acc[0]); acc[1] = ffma2(vp, wa.y, acc[1]);
                acc[2] = ffma2(vp, wb.x, acc[2]); acc[3] = ffma2(vp, wb.y, acc[3]);
            }
        }
    }
    float out[8];
    #pragma unroll
    for (int k = 0; k < 4; k++) unpk(acc[k], out[2*k], out[2*k+1]);
    #pragma unroll
    for (int c = 0; c < 8; c++) out[c] = fmaxf(out[c] + sbeta[c], 0.f);
    int n = (y0 + ty)*64 + (x0 + tx);
    float4* dst = (float4*)&g_nodes[((size_t)b*NN + n)*16 + oh*8];
    dst[0] = make_float4(out[0],out[1],out[2],out[3]);
    dst[1] = make_float4(out[4],out[5],out[6],out[7]);
}

// ----------------- GAT feature transform + 0.5*|n|^2 -----------------
__global__ void featk(const float* __restrict__ Wg, const float* __restrict__ a_src,
                      const float* __restrict__ a_dst)
{
    __shared__ float sWg[256];
    __shared__ float ssrc[16], sdst[16];
    int t = threadIdx.x;
    sWg[t] = Wg[t];
    if (t < 16) { ssrc[t] = a_src[t]; sdst[t] = a_dst[t]; }
    __syncthreads();
    int idx = blockIdx.x * 256 + t;
    const float4* np = (const float4*)&g_nodes[(size_t)idx*16];
    float n[16];
    float4 v0 = np[0], v1 = np[1], v2 = np[2], v3 = np[3];
    n[0]=v0.x; n[1]=v0.y; n[2]=v0.z; n[3]=v0.w;
    n[4]=v1.x; n[5]=v1.y; n[6]=v1.z; n[7]=v1.w;
    n[8]=v2.x; n[9]=v2.y; n[10]=v2.z; n[11]=v2.w;
    n[12]=v3.x; n[13]=v3.y; n[14]=v3.z; n[15]=v3.w;
    float s = 0.f;
    #pragma unroll
    for (int c = 0; c < 16; c++) s = fmaf(n[c], n[c], s);
    g_sq[idx] = 0.5f * s;
    float xo[16];
    #pragma unroll
    for (int o = 0; o < 16; o++) {
        float a = 0.f;
        #pragma unroll
        for (int c = 0; c < 16; c++) a = fmaf(n[c], sWg[o*16 + c], a);
        xo[o] = a;
    }
    float4* xpd = (float4*)&g_xp[(size_t)idx*16];
    xpd[0] = make_float4(xo[0],xo[1],xo[2],xo[3]);
    xpd[1] = make_float4(xo[4],xo[5],xo[6],xo[7]);
    xpd[2] = make_float4(xo[8],xo[9],xo[10],xo[11]);
    xpd[3] = make_float4(xo[12],xo[13],xo[14],xo[15]);
    float4 av, dv;
    av.x = xo[0]*ssrc[0] + xo[1]*ssrc[1] + xo[2]*ssrc[2] + xo[3]*ssrc[3];
    av.y = xo[4]*ssrc[4] + xo[5]*ssrc[5] + xo[6]*ssrc[6] + xo[7]*ssrc[7];
    av.z = xo[8]*ssrc[8] + xo[9]*ssrc[9] + xo[10]*ssrc[10] + xo[11]*ssrc[11];
    av.w = xo[12]*ssrc[12] + xo[13]*ssrc[13] + xo[14]*ssrc[14] + xo[15]*ssrc[15];
    dv.x = xo[0]*sdst[0] + xo[1]*sdst[1] + xo[2]*sdst[2] + xo[3]*sdst[3];
    dv.y = xo[4]*sdst[4] + xo[5]*sdst[5] + xo[6]*sdst[6] + xo[7]*sdst[7];
    dv.z = xo[8]*sdst[8] + xo[9]*sdst[9] + xo[10]*sdst[10] + xo[11]*sdst[11];
    dv.w = xo[12]*sdst[12] + xo[13]*sdst[13] + xo[14]*sdst[14] + xo[15]*sdst[15];
    ((float4*)g_asr)[idx] = av;
    ((float4*)g_adt)[idx] = dv;
}

// ----------------- kNN top-8 + GAT: tau-gated, packed 2-cand epilogue -----------------
__global__ void __launch_bounds__(64) knnk(const float* __restrict__ bg)
{
    // sfeat: component-pair-major transposed tile:
    //   float addr = (k>>1)*256 + jp*4 + (k&1)*2 + parity   (k=component, jp=pair, parity=cand&1)
    //   -> ulonglong2 at index (k2*64 + jp) = (cand_even[2k2],cand_odd[2k2], cand_even[2k2+1],cand_odd[2k2+1])
    __shared__ __align__(16) float sfeat[2048];   // 8 KB, 128 candidates
    __shared__ __align__(8)  float ssq[128];
    int t = threadIdx.x;
    int b = blockIdx.y;
    int row = blockIdx.x * 64 + t;
    const float* nbase = g_nodes + (size_t)b * NN * 16;
    const float* sqb = g_sq + (size_t)b * NN;

    float nv[16];
    {
        const float4* rp = (const float4*)(nbase + (size_t)row*16);
        float4 f0 = rp[0], f1 = rp[1], f2 = rp[2], f3 = rp[3];
        nv[0]=-f0.x; nv[1]=-f0.y; nv[2]=-f0.z; nv[3]=-f0.w;
        nv[4]=-f1.x; nv[5]=-f1.y; nv[6]=-f1.z; nv[7]=-f1.w;
        nv[8]=-f2.x; nv[9]=-f2.y; nv[10]=-f2.z; nv[11]=-f2.w;
        nv[12]=-f3.x; nv[13]=-f3.y; nv[14]=-f3.z; nv[15]=-f3.w;
    }
    unsigned long long rneg[16];
    #pragma unroll
    for (int k = 0; k < 16; k++) rneg[k] = pk2(nv[k], nv[k]);

    // ---- tau pre-pass: 24 distinct spatial neighbours (5x5 window minus self) ----
    float td[8];
    #pragma unroll
    for (int p = 0; p < 8; p++) td[p] = 3e38f;
    {
        int y = row >> 6, x = row & 63;
        int sy = y - 2; sy = sy < 0 ? 0 : (sy > 59 ? 59 : sy);
        int sx = x - 2; sx = sx < 0 ? 0 : (sx > 59 ? 59 : sx);
        for (int dy = 0; dy < 5; dy++) {
            for (int dx = 0; dx < 5; dx++) {
                int n = (sy+dy)*64 + (sx+dx);
                if (n == row) continue;
                const float* cp = nbase + (size_t)n*16;
                float acc = sqb[n];
                #pragma unroll
                for (int k = 0; k < 16; k++) acc = fmaf(nv[k], cp[k], acc);
                if (acc < td[7]) {
                    td[7] = acc;
                    #pragma unroll
                    for (int p = 7; p > 0; p--)
                        if (td[p] < td[p-1]) { float tmp = td[p]; td[p] = td[p-1]; td[p-1] = tmp; }
                }
            }
        }
    }
    float tau = td[7];

    float bd[8]; int bi[8];
    #pragma unroll
    for (int p = 0; p < 8; p++) { bd[p] = 3e38f; bi[p] = 0; }
    float gate = tau;

    for (int tt = 0; tt < 32; tt++) {
        __syncthreads();
        #pragma unroll
        for (int half = 0; half < 2; half++) {
            int lc = half*64 + t;                 // local candidate 0..127
            int c = tt*128 + lc;
            const float4* src = (const float4*)(nbase + (size_t)c*16);
            float4 q0 = src[0], q1 = src[1], q2 = src[2], q3 = src[3];
            float vals[16] = {q0.x,q0.y,q0.z,q0.w, q1.x,q1.y,q1.z,q1.w,
                              q2.x,q2.y,q2.z,q2.w, q3.x,q3.y,q3.z,q3.w};
            int jp = lc >> 1, par = lc & 1;
            #pragma unroll
            for (int k = 0; k < 16; k++)
                sfeat[(k>>1)*256 + jp*4 + (k&1)*2 + par] = vals[k];
            ssq[lc] = sqb[c];
        }
        __syncthreads();
        const ulonglong2* fb = (const ulonglong2*)sfeat;
        const unsigned long long* sqp = (const unsigned long long*)ssq;
        int cb = tt * 128;
        #pragma unroll 2
        for (int jp = 0; jp < 64; jp++) {
            unsigned long long acc = sqp[jp];
            ulonglong2 w;
            w = fb[      jp]; acc = ffma2(rneg[0],  w.x, acc); acc = ffma2(rneg[1],  w.y, acc);
            w = fb[ 64 + jp]; acc = ffma2(rneg[2],  w.x, acc); acc = ffma2(rneg[3],  w.y, acc);
            w = fb[128 + jp]; acc = ffma2(rneg[4],  w.x, acc); acc = ffma2(rneg[5],  w.y, acc);
            w = fb[192 + jp]; acc = ffma2(rneg[6],  w.x, acc); acc = ffma2(rneg[7],  w.y, acc);
            w = fb[256 + jp]; acc = ffma2(rneg[8],  w.x, acc); acc = ffma2(rneg[9],  w.y, acc);
            w = fb[320 + jp]; acc = ffma2(rneg[10], w.x, acc); acc = ffma2(rneg[11], w.y, acc);
            w = fb[384 + jp]; acc = ffma2(rneg[12], w.x, acc); acc = ffma2(rneg[13], w.y, acc);
            w = fb[448 + jp]; acc = ffma2(rneg[14], w.x, acc); acc = ffma2(rneg[15], w.y, acc);
            float dlo, dhi; unpk(acc, dlo, dhi);
            if (fminf(dlo, dhi) <= gate) {
                int j0 = cb + jp*2;
                if (dlo < bd[7] && j0 != row) {
                    bd[7] = dlo; bi[7] = j0;
                    #pragma unroll
                    for (int p = 7; p > 0; p--)
                        if (bd[p] < bd[p-1]) {
                            float tmp = bd[p]; bd[p] = bd[p-1]; bd[p-1] = tmp;
                            int ti = bi[p]; bi[p] = bi[p-1]; bi[p-1] = ti;
                        }
                }
                if (dhi < bd[7] && (j0+1) != row) {
                    bd[7] = dhi; bi[7] = j0+1;
                    #pragma unroll
                    for (int p = 7; p > 0; p--)
                        if (bd[p] < bd[p-1]) {
                            float tmp = bd[p]; bd[p] = bd[p-1]; bd[p-1] = tmp;
                            int ti = bi[p]; bi[p] = bi[p-1]; bi[p-1] = ti;
                        }
                }
                gate = fminf(tau, bd[7]);
            }
        }
    }

    // ---- GAT aggregation over 8 neighbors + self ----
    float4 adv = ((const float4*)g_adt)[b*NN + row];
    float ad0 = adv.x, ad1 = adv.y, ad2 = adv.z, ad3 = adv.w;
    int idxs[9];
    #pragma unroll
    for (int k = 0; k < 8; k++) idxs[k] = bi[k];
    idxs[8] = row;
    float lg[36];
    float m0 = -3e38f, m1 = -3e38f, m2 = -3e38f, m3 = -3e38f;
    #pragma unroll
    for (int k = 0; k < 9; k++) {
        float4 av = ((const float4*)g_asr)[b*NN + idxs[k]];
        float l0 = av.x + ad0; l0 = l0 > 0.f ? l0 : 0.2f*l0;
        float l1 = av.y + ad1; l1 = l1 > 0.f ? l1 : 0.2f*l1;
        float l2 = av.z + ad2; l2 = l2 > 0.f ? l2 : 0.2f*l2;
        float l3 = av.w + ad3; l3 = l3 > 0.f ? l3 : 0.2f*l3;
        lg[k*4+0] = l0; lg[k*4+1] = l1; lg[k*4+2] = l2; lg[k*4+3] = l3;
        m0 = fmaxf(m0, l0); m1 = fmaxf(m1, l1); m2 = fmaxf(m2, l2); m3 = fmaxf(m3, l3);
    }
    float s0 = 0.f, s1 = 0.f, s2 = 0.f, s3 = 0.f;
    float out[16];
    #pragma unroll
    for (int c = 0; c < 16; c++) out[c] = 0.f;
    #pragma unroll
    for (int k = 0; k < 9; k++) {
        float w0 = expf(lg[k*4+0] - m0);
        float w1 = expf(lg[k*4+1] - m1);
        float w2 = expf(lg[k*4+2] - m2);
        float w3 = expf(lg[k*4+3] - m3);
        s0 += w0; s1 += w1; s2 += w2; s3 += w3;
        const float4* xp4 = (const float4*)g_xp + ((size_t)b*NN + idxs[k])*4;
        float4 x0 = xp4[0], x1 = xp4[1], x2 = xp4[2], x3 = xp4[3];
        out[0]  = fmaf(w0, x0.x, out[0]);  out[1]  = fmaf(w0, x0.y, out[1]);
        out[2]  = fmaf(w0, x0.z, out[2]);  out[3]  = fmaf(w0, x0.w, out[3]);
        out[4]  = fmaf(w1, x1.x, out[4]);  out[5]  = fmaf(w1, x1.y, out[5]);
        out[6]  = fmaf(w1, x1.z, out[6]);  out[7]  = fmaf(w1, x1.w, out[7]);
        out[8]  = fmaf(w2, x2.x, out[8]);  out[9]  = fmaf(w2, x2.y, out[9]);
        out[10] = fmaf(w2, x2.z, out[10]); out[11] = fmaf(w2, x2.w, out[11]);
        out[12] = fmaf(w3, x3.x, out[12]); out[13] = fmaf(w3, x3.y, out[13]);
        out[14] = fmaf(w3, x3.z, out[14]); out[15] = fmaf(w3, x3.w, out[15]);
    }
    float inv0 = 1.f/s0, inv1 = 1.f/s1, inv2 = 1.f/s2, inv3 = 1.f/s3;
    float res[16];
    #pragma unroll
    for (int c = 0; c < 4;  c++) res[c] = fmaxf(out[c]*inv0 + bg[c], 0.f);
    #pragma unroll
    for (int c = 4; c < 8;  c++) res[c] = fmaxf(out[c]*inv1 + bg[c], 0.f);
    #pragma unroll
    for (int c = 8; c < 12; c++) res[c] = fmaxf(out[c]*inv2 + bg[c], 0.f);
    #pragma unroll
    for (int c = 12; c < 16; c++) res[c] = fmaxf(out[c]*inv3 + bg[c], 0.f);
    float4* pd = (float4*)g_p + ((size_t)b*NN + row)*4;
    pd[0] = make_float4(res[0],res[1],res[2],res[3]);
    pd[1] = make_float4(res[4],res[5],res[6],res[7]);
    pd[2] = make_float4(res[8],res[9],res[10],res[11]);
    pd[3] = make_float4(res[12],res[13],res[14],res[15]);
}

// ----------------- update MLP + fire mask + output conv + sigmoid -----------------
__global__ void updk(const float* __restrict__ fire, const float* __restrict__ Wu1,
                     const float* __restrict__ bu1, const float* __restrict__ bu2,
                     const float* __restrict__ Wo,  const float* __restrict__ bo)
{
    __shared__ __align__(16) float sW1[2048];
    __shared__ __align__(16) float sW2[2048];
    __shared__ __align__(16) float sb2[16];
    __shared__ __align__(16) float sWo[16];
    __shared__ float sb1[128];
    __shared__ float sbo;
    int t = threadIdx.x;
    for (int i = t; i < 2048; i += 256) { sW1[i] = Wu1[i]; sW2[i] = g_Wu2t[i]; }
    if (t < 128) sb1[t] = bu1[t];
    if (t < 16)  { sb2[t] = bu2[t]; sWo[t] = Wo[t]; }
    if (t == 0)  sbo = bo[0];
    __syncthreads();
    int idx = blockIdx.x * 256 + t;
    const ulonglong2* pp = (const ulonglong2*)(g_p + (size_t)idx*16);
    ulonglong2 p0 = pp[0], p1 = pp[1], p2 = pp[2], p3 = pp[3];
    unsigned long long pk[8] = {p0.x,p0.y,p1.x,p1.y,p2.x,p2.y,p3.x,p3.y};
    unsigned long long u[8];
    {
        const ulonglong2* b2p = (const ulonglong2*)sb2;
        ulonglong2 u0 = b2p[0], u1 = b2p[1];
        u[0]=u0.x; u[1]=u0.y; u[2]=u1.x; u[3]=u1.y;
        ulonglong2 u2 = b2p[2], u3 = b2p[3];
        u[4]=u2.x; u[5]=u2.y; u[6]=u3.x; u[7]=u3.y;
    }
    #pragma unroll 2
    for (int h = 0; h < 128; h++) {
        const ulonglong2* w1p = (const ulonglong2*)&sW1[h*16];
        ulonglong2 wa = w1p[0], wb = w1p[1], wc = w1p[2], wd = w1p[3];
        unsigned long long acc = ffma2(pk[0], wa.x, 0ull);
        acc = ffma2(pk[1], wa.y, acc);
        acc = ffma2(pk[2], wb.x, acc);
        acc = ffma2(pk[3], wb.y, acc);
        acc = ffma2(pk[4], wc.x, acc);
        acc = ffma2(pk[5], wc.y, acc);
        acc = ffma2(pk[6], wd.x, acc);
        acc = ffma2(pk[7], wd.y, acc);
        float a = unpksum(acc) + sb1[h];
        a = fmaxf(a, 0.f);
        unsigned long long ap = pk2(a, a);
        const ulonglong2* w2p = (const ulonglong2*)&sW2[h*16];
        ulonglong2 va = w2p[0], vb = w2p[1], vc = w2p[2], vd = w2p[3];
        u[0] = ffma2(ap, va.x, u[0]); u[1] = ffma2(ap, va.y, u[1]);
        u[2] = ffma2(ap, vb.x, u[2]); u[3] = ffma2(ap, vb.y, u[3]);
        u[4] = ffma2(ap, vc.x, u[4]); u[5] = ffma2(ap, vc.y, u[5]);
        u[6] = ffma2(ap, vd.x, u[6]); u[7] = ffma2(ap, vd.y, u[7]);
    }
    float mask = fire[idx] < 0.5f ? 1.f : 0.f;
    unsigned long long mp = pk2(mask, mask);
    const ulonglong2* hp = (const ulonglong2*)(g_nodes + (size_t)idx*16);
    ulonglong2 h0 = hp[0], h1 = hp[1], h2 = hp[2], h3 = hp[3];
    unsigned long long hk[8] = {h0.x,h0.y,h1.x,h1.y,h2.x,h2.y,h3.x,h3.y};
    const ulonglong2* wop = (const ulonglong2*)sWo;
    ulonglong2 wo0 = wop[0], wo1 = wop[1], wo2 = wop[2], wo3 = wop[3];
    unsigned long long wk[8] = {wo0.x,wo0.y,wo1.x,wo1.y,wo2.x,wo2.y,wo3.x,wo3.y};
    unsigned long long accS = 0ull;
    #pragma unroll
    for (int k = 0; k < 8; k++) {
        unsigned long long hn = ffma2(mp, u[k], hk[k]);
        accS = ffma2(wk[k], hn, accS);
    }
    float ss = unpksum(accS) + sbo;
    g_outlow[idx] = 1.f / (1.f + expf(-ss));
}

// ----------------- bilinear 64 -> 256 -----------------
__global__ void upk(float* __restrict__ out)
{
    int idx = blockIdx.x * 256 + threadIdx.x;
    int b = idx >> 16, oy = (idx >> 8) & 255, ox = idx & 255;
    float sy = (oy + 0.5f) * 0.25f - 0.5f;
    float sx = (ox + 0.5f) * 0.25f - 0.5f;
    int y0 = (int)floorf(sy); float fy = sy - (float)y0;
    int x0 = (int)floorf(sx); float fx = sx - (float)x0;
    float wy0 = 1.f - fy, wy1 = fy; int y1 = y0 + 1;
    float wx0 = 1.f - fx, wx1 = fx; int x1 = x0 + 1;
    if (y0 < 0)  { wy0 = 0.f; y0 = 0; }
    if (y1 > 63) { wy1 = 0.f; y1 = 63; }
    if (x0 < 0)  { wx0 = 0.f; x0 = 0; }
    if (x1 > 63) { wx1 = 0.f; x1 = 63; }
    const float* src = g_outlow + b * 4096;
    float v = wy0 * (wx0 * src[y0*64 + x0] + wx1 * src[y0*64 + x1])
            + wy1 * (wx0 * src[y1*64 + x0] + wx1 * src[y1*64 + x1]);
    out[idx] = v / ((wy0 + wy1) * (wx0 + wx1));
}

// ----------------- launch -----------------
extern "C" void kernel_launch(void* const* d_in, const int* in_sizes, int n_in,
                              void* d_out, int out_size)
{
    (void)in_sizes; (void)n_in; (void)out_size;
    const float* x    = (const float*)d_in[0];
    const float* fire = (const float*)d_in[1];
    const float* W1   = (const float*)d_in[2];
    const float* b1   = (const float*)d_in[3];
    const float* g1   = (const float*)d_in[4];
    const float* be1  = (const float*)d_in[5];
    const float* m1   = (const float*)d_in[6];
    const float* v1   = (const float*)d_in[7];
    const float* W2   = (const float*)d_in[8];
    const float* b2   = (const float*)d_in[9];
    const float* g2   = (const float*)d_in[10];
    const float* be2  = (const float*)d_in[11];
    const float* m2   = (const float*)d_in[12];
    const float* v2   = (const float*)d_in[13];
    const float* Wg   = (const float*)d_in[14];
    const float* a_src= (const float*)d_in[15];
    const float* a_dst= (const float*)d_in[16];
    const float* bg   = (const float*)d_in[17];
    const float* Wu1  = (const float*)d_in[18];
    const float* bu1  = (const float*)d_in[19];
    const float* Wu2  = (const float*)d_in[20];
    const float* bu2  = (const float*)d_in[21];
    const float* Wo   = (const float*)d_in[22];
    const float* bo   = (const float*)d_in[23];
    float* out = (float*)d_out;

    prepk<<<1, 256>>>(W1, b1, g1, be1, m1, v1, W2, b2, g2, be2, m2, v2, Wu2);
    downk<<<128, 256>>>(x);
    conv1k<<<128, 256>>>();
    conv2k<<<dim3(8, 8, 8), 128>>>();
    featk<<<128, 256>>>(Wg, a_src, a_dst);
    knnk<<<dim3(64, 8), 64>>>(bg);
    updk<<<128, 256>>>(fire, Wu1, bu1, bu2, Wo, bo);
    upk<<<2048, 256>>>(out);
}